// round 15
// baseline (speedup 1.0000x reference)
#include <cuda_runtime.h>
#include <cuda_bf16.h>

// ChamferDistance: B=8, N=4096, D=3.
// Round 15: round 14 (41.4us) spent ~8us on the separate sum kernel (launch +
// latency overhead; issue 2.8%). Fuse the final decode/sum into the pair
// kernel via last-block-done: the 1024th block to finish decodes all 65536
// encoded mins (uint4, unrolled high-MLP L2 reads), fixed-order sums, writes
// the scalar, and resets all state for graph replay. One launch total.
// Inner loop unchanged: pair-once packed FFMA2 + redux.sync.max.u32 col-min.

#define CD_B 8
#define CD_N 4096
#define CD_TPB 128
#define CD_Q 8
#define CD_QBLK (CD_TPB * CD_Q)          // 1024 queries per block
#define CD_NQB (CD_N / CD_QBLK)          // 4
#define CD_TSPLIT 32
#define CD_TPTS (CD_N / CD_TSPLIT)       // 128 targets per block
#define CD_TPAIRS (CD_TPTS / 2)          // 64 packed pairs
#define CD_SLOTS (2 * CD_B * CD_N)       // 65536 (rows then cols)
#define CD_COL_BASE (CD_B * CD_N)
#define CD_NBLOCKS (CD_NQB * CD_TSPLIT * CD_B)   // 1024
#define CD_U4 (CD_SLOTS / 4)             // 16384 uint4
#define CD_U4PT (CD_U4 / CD_TPB)         // 128 per thread in final block

__device__ unsigned int g_min[CD_SLOTS]; // encoded mins; zero-init; self-reset
__device__ unsigned int g_fcnt;

typedef unsigned long long u64;

__device__ __forceinline__ u64 pack2(float v) {
    u64 r;
    unsigned int u = __float_as_uint(v);
    asm("mov.b64 %0, {%1, %1};" : "=l"(r) : "r"(u));
    return r;
}

__device__ __forceinline__ u64 fma2(u64 a, u64 b, u64 c) {
    u64 d;
    asm("fma.rn.f32x2 %0, %1, %2, %3;" : "=l"(d) : "l"(a), "l"(b), "l"(c));
    return d;
}

__device__ __forceinline__ u64 add2(u64 a, u64 b) {
    u64 d;
    asm("add.rn.f32x2 %0, %1, %2;" : "=l"(d) : "l"(a), "l"(b));
    return d;
}

__device__ __forceinline__ void unpack2(u64 v, float& lo, float& hi) {
    unsigned int l, h;
    asm("mov.b64 {%0, %1}, %2;" : "=r"(l), "=r"(h) : "l"(v));
    lo = __uint_as_float(l);
    hi = __uint_as_float(h);
}

__device__ __forceinline__ unsigned int redux_max(unsigned int v) {
    unsigned int d;
    asm("redux.sync.max.u32 %0, %1, 0xffffffff;" : "=r"(d) : "r"(v));
    return d;
}

__global__ __launch_bounds__(CD_TPB, 4)
void cd_pair_kernel(const float* __restrict__ p1,
                    const float* __restrict__ p2,
                    float* __restrict__ out) {
    __shared__ float4 sy[CD_TPTS];       // pair-interleaved target tile (2KB)
    __shared__ float red[CD_TPB];
    __shared__ int s_flag;

    const int tid  = threadIdx.x;
    const int ts   = blockIdx.x % CD_TSPLIT;
    const int qblk = blockIdx.x / CD_TSPLIT;
    const int b    = blockIdx.y;

    // Q=8 query points from p1; fold -2 into packed coords; xd packed too.
    u64 xq0[CD_Q], xq1[CD_Q], xq2[CD_Q], xd2[CD_Q];
    float mlo[CD_Q], mhi[CD_Q];
    #pragma unroll
    for (int q = 0; q < CD_Q; q++) {
        const int i = qblk * CD_QBLK + q * CD_TPB + tid;
        const float* xp = p1 + ((size_t)b * CD_N + i) * 3;
        const float x0 = xp[0], x1 = xp[1], x2 = xp[2];
        xd2[q] = pack2(x0 * x0 + x1 * x1 + x2 * x2);
        xq0[q] = pack2(-2.0f * x0);
        xq1[q] = pack2(-2.0f * x1);
        xq2[q] = pack2(-2.0f * x2);
        mlo[q] = 3.402823466e38f;
        mhi[q] = 3.402823466e38f;
    }

    // Target tile from p2 (one pair per thread, first 64 threads).
    if (tid < CD_TPAIRS) {
        const float* yp = p2 + ((size_t)b * CD_N + ts * CD_TPTS + 2 * tid) * 3;
        float e0 = yp[0], e1 = yp[1], e2 = yp[2];
        float o0 = yp[3], o1 = yp[4], o2 = yp[5];
        sy[2 * tid]     = make_float4(e0, o0, e1, o1);
        sy[2 * tid + 1] = make_float4(e2, o2,
                                      e0 * e0 + e1 * e1 + e2 * e2,
                                      o0 * o0 + o1 * o1 + o2 * o2);
    }
    __syncthreads();

    const ulonglong2* __restrict__ syu = reinterpret_cast<const ulonglong2*>(sy);
    const int lane = tid & 31;
    const int colbase = CD_COL_BASE + b * CD_N + ts * CD_TPTS;

    #pragma unroll 2
    for (int p = 0; p < CD_TPAIRS; p++) {
        ulonglong2 A  = syu[2 * p];      // y0 pair, y1 pair
        ulonglong2 Bv = syu[2 * p + 1];  // y2 pair, yd pair
        float ce = 3.402823466e38f, co = 3.402823466e38f;
        #pragma unroll
        for (int q = 0; q < CD_Q; q++) {
            u64 d = fma2(xq2[q], Bv.x, Bv.y);
            d = fma2(xq1[q], A.y, d);
            d = fma2(xq0[q], A.x, d);
            u64 e = add2(d, xd2[q]);     // full dist^2 (lo=target e, hi=target o)
            float elo, ehi;
            unpack2(e, elo, ehi);
            mlo[q] = fminf(mlo[q], elo); // row mins (query-private)
            mhi[q] = fminf(mhi[q], ehi);
            ce = fminf(ce, elo);         // col candidates for this target pair
            co = fminf(co, ehi);
        }
        // Warp col-min in ONE instruction on the encoded key, then lane0 atomic.
        unsigned int ke = redux_max(~__float_as_uint(fmaxf(ce, 0.0f)));
        unsigned int ko = redux_max(~__float_as_uint(fmaxf(co, 0.0f)));
        if (lane == 0) {
            atomicMax(&g_min[colbase + 2 * p], ke);
            atomicMax(&g_min[colbase + 2 * p + 1], ko);
        }
    }

    // Row mins: one encoded atomicMax per query.
    #pragma unroll
    for (int q = 0; q < CD_Q; q++) {
        const int i = qblk * CD_QBLK + q * CD_TPB + tid;
        float v = fmaxf(fminf(mlo[q], mhi[q]), 0.0f);
        atomicMax(&g_min[b * CD_N + i], ~__float_as_uint(v));
    }

    // Last-block-done: decode + fixed-order sum + reset, all in this launch.
    __threadfence();
    if (tid == 0) {
        unsigned int t = atomicAdd(&g_fcnt, 1u);
        s_flag = (t == CD_NBLOCKS - 1);
    }
    __syncthreads();

    if (s_flag) {
        uint4* gm4 = reinterpret_cast<uint4*>(g_min);
        float acc = 0.0f;
        #pragma unroll 8
        for (int k = 0; k < CD_U4PT; k++) {
            const int idx = k * CD_TPB + tid;         // coalesced, high MLP
            uint4 kk = gm4[idx];
            acc += __uint_as_float(~kk.x) + __uint_as_float(~kk.y)
                 + __uint_as_float(~kk.z) + __uint_as_float(~kk.w);
            gm4[idx] = make_uint4(0u, 0u, 0u, 0u);    // reset for graph replay
        }
        red[tid] = acc;
        __syncthreads();
        #pragma unroll
        for (int s = CD_TPB / 2; s > 0; s >>= 1) {
            if (tid < s) red[tid] += red[tid + s];
            __syncthreads();
        }
        if (tid == 0) {
            out[0] = red[0] * (1.0f / ((float)CD_B * (float)CD_N));
            g_fcnt = 0;                               // reset for graph replay
        }
    }
}

extern "C" void kernel_launch(void* const* d_in, const int* in_sizes, int n_in,
                              void* d_out, int out_size) {
    (void)in_sizes; (void)n_in; (void)out_size;
    const float* p1 = (const float*)d_in[0];
    const float* p2 = (const float*)d_in[1];
    float* out = (float*)d_out;

    dim3 grid(CD_NQB * CD_TSPLIT, CD_B);   // 128 x 8 = 1024 blocks
    cd_pair_kernel<<<grid, CD_TPB>>>(p1, p2, out);
}

// round 16
// speedup vs baseline: 1.1908x; 1.1908x over previous
#include <cuda_runtime.h>
#include <cuda_bf16.h>

// ChamferDistance: B=8, N=4096, D=3.
// Round 16: revert round-15 fusion (tail register pressure wrecked the
// mainloop's compile: regs 96, fma 50->29%, 33->52us). Round-14 pair kernel
// kept BYTE-IDENTICAL. The 8us sum kernel (512 one-load warps, MLP=1, two
// global stages) is replaced by a single 512-thread block: 32 uint4 loads per
// thread (deep MLP), decode+reset, one fixed-order in-block reduction.
// No threadfence/second stage. Deterministic throughout.

#define CD_B 8
#define CD_N 4096
#define CD_TPB 128
#define CD_Q 8
#define CD_QBLK (CD_TPB * CD_Q)          // 1024 queries per block
#define CD_NQB (CD_N / CD_QBLK)          // 4
#define CD_TSPLIT 32
#define CD_TPTS (CD_N / CD_TSPLIT)       // 128 targets per block
#define CD_TPAIRS (CD_TPTS / 2)          // 64 packed pairs
#define CD_SLOTS (2 * CD_B * CD_N)       // 65536 (rows then cols)
#define CD_COL_BASE (CD_B * CD_N)
#define CD_STPB 512
#define CD_U4 (CD_SLOTS / 4)             // 16384 uint4
#define CD_U4PT (CD_U4 / CD_STPB)        // 32 per thread

__device__ unsigned int g_min[CD_SLOTS]; // encoded mins; zero-init; self-reset

typedef unsigned long long u64;

__device__ __forceinline__ u64 pack2(float v) {
    u64 r;
    unsigned int u = __float_as_uint(v);
    asm("mov.b64 %0, {%1, %1};" : "=l"(r) : "r"(u));
    return r;
}

__device__ __forceinline__ u64 fma2(u64 a, u64 b, u64 c) {
    u64 d;
    asm("fma.rn.f32x2 %0, %1, %2, %3;" : "=l"(d) : "l"(a), "l"(b), "l"(c));
    return d;
}

__device__ __forceinline__ u64 add2(u64 a, u64 b) {
    u64 d;
    asm("add.rn.f32x2 %0, %1, %2;" : "=l"(d) : "l"(a), "l"(b));
    return d;
}

__device__ __forceinline__ void unpack2(u64 v, float& lo, float& hi) {
    unsigned int l, h;
    asm("mov.b64 {%0, %1}, %2;" : "=r"(l), "=r"(h) : "l"(v));
    lo = __uint_as_float(l);
    hi = __uint_as_float(h);
}

// Warp-wide max of a u32 in one instruction (sm_80+ REDUX unit).
__device__ __forceinline__ unsigned int redux_max(unsigned int v) {
    unsigned int d;
    asm("redux.sync.max.u32 %0, %1, 0xffffffff;" : "=r"(d) : "r"(v));
    return d;
}

__global__ __launch_bounds__(CD_TPB, 4)
void cd_pair_kernel(const float* __restrict__ p1,
                    const float* __restrict__ p2) {
    __shared__ float4 sy[CD_TPTS];       // pair-interleaved target tile (2KB)

    const int tid  = threadIdx.x;
    const int ts   = blockIdx.x % CD_TSPLIT;
    const int qblk = blockIdx.x / CD_TSPLIT;
    const int b    = blockIdx.y;

    // Q=8 query points from p1; fold -2 into packed coords; xd packed too.
    u64 xq0[CD_Q], xq1[CD_Q], xq2[CD_Q], xd2[CD_Q];
    float mlo[CD_Q], mhi[CD_Q];
    #pragma unroll
    for (int q = 0; q < CD_Q; q++) {
        const int i = qblk * CD_QBLK + q * CD_TPB + tid;
        const float* xp = p1 + ((size_t)b * CD_N + i) * 3;
        const float x0 = xp[0], x1 = xp[1], x2 = xp[2];
        xd2[q] = pack2(x0 * x0 + x1 * x1 + x2 * x2);
        xq0[q] = pack2(-2.0f * x0);
        xq1[q] = pack2(-2.0f * x1);
        xq2[q] = pack2(-2.0f * x2);
        mlo[q] = 3.402823466e38f;
        mhi[q] = 3.402823466e38f;
    }

    // Target tile from p2 (one pair per thread, first 64 threads).
    if (tid < CD_TPAIRS) {
        const float* yp = p2 + ((size_t)b * CD_N + ts * CD_TPTS + 2 * tid) * 3;
        float e0 = yp[0], e1 = yp[1], e2 = yp[2];
        float o0 = yp[3], o1 = yp[4], o2 = yp[5];
        sy[2 * tid]     = make_float4(e0, o0, e1, o1);
        sy[2 * tid + 1] = make_float4(e2, o2,
                                      e0 * e0 + e1 * e1 + e2 * e2,
                                      o0 * o0 + o1 * o1 + o2 * o2);
    }
    __syncthreads();

    const ulonglong2* __restrict__ syu = reinterpret_cast<const ulonglong2*>(sy);
    const int lane = tid & 31;
    const int colbase = CD_COL_BASE + b * CD_N + ts * CD_TPTS;

    #pragma unroll 2
    for (int p = 0; p < CD_TPAIRS; p++) {
        ulonglong2 A  = syu[2 * p];      // y0 pair, y1 pair
        ulonglong2 Bv = syu[2 * p + 1];  // y2 pair, yd pair
        float ce = 3.402823466e38f, co = 3.402823466e38f;
        #pragma unroll
        for (int q = 0; q < CD_Q; q++) {
            u64 d = fma2(xq2[q], Bv.x, Bv.y);
            d = fma2(xq1[q], A.y, d);
            d = fma2(xq0[q], A.x, d);
            u64 e = add2(d, xd2[q]);     // full dist^2 (lo=target e, hi=target o)
            float elo, ehi;
            unpack2(e, elo, ehi);
            mlo[q] = fminf(mlo[q], elo); // row mins (query-private)
            mhi[q] = fminf(mhi[q], ehi);
            ce = fminf(ce, elo);         // col candidates for this target pair
            co = fminf(co, ehi);
        }
        // Warp col-min in ONE instruction on the encoded key, then lane0 atomic.
        unsigned int ke = redux_max(~__float_as_uint(fmaxf(ce, 0.0f)));
        unsigned int ko = redux_max(~__float_as_uint(fmaxf(co, 0.0f)));
        if (lane == 0) {
            atomicMax(&g_min[colbase + 2 * p], ke);
            atomicMax(&g_min[colbase + 2 * p + 1], ko);
        }
    }

    // Row mins: one encoded atomicMax per query.
    #pragma unroll
    for (int q = 0; q < CD_Q; q++) {
        const int i = qblk * CD_QBLK + q * CD_TPB + tid;
        float v = fmaxf(fminf(mlo[q], mhi[q]), 0.0f);
        atomicMax(&g_min[b * CD_N + i], ~__float_as_uint(v));
    }
}

// Single block, deep-MLP decode + fixed-order sum + reset.
__global__ __launch_bounds__(CD_STPB)
void cd_sum_kernel(float* __restrict__ out) {
    __shared__ float red[CD_STPB];
    const int tid = threadIdx.x;
    uint4* gm4 = reinterpret_cast<uint4*>(g_min);

    float acc = 0.0f;
    #pragma unroll
    for (int k = 0; k < CD_U4PT; k++) {                   // 32 loads in flight
        const int idx = k * CD_STPB + tid;                // coalesced
        uint4 kk = gm4[idx];
        acc += __uint_as_float(~kk.x) + __uint_as_float(~kk.y)
             + __uint_as_float(~kk.z) + __uint_as_float(~kk.w);
        gm4[idx] = make_uint4(0u, 0u, 0u, 0u);            // reset for replay
    }
    red[tid] = acc;
    __syncthreads();
    #pragma unroll
    for (int s = CD_STPB / 2; s > 0; s >>= 1) {
        if (tid < s) red[tid] += red[tid + s];
        __syncthreads();
    }
    if (tid == 0)
        out[0] = red[0] * (1.0f / ((float)CD_B * (float)CD_N));
}

extern "C" void kernel_launch(void* const* d_in, const int* in_sizes, int n_in,
                              void* d_out, int out_size) {
    (void)in_sizes; (void)n_in; (void)out_size;
    const float* p1 = (const float*)d_in[0];
    const float* p2 = (const float*)d_in[1];
    float* out = (float*)d_out;

    dim3 grid(CD_NQB * CD_TSPLIT, CD_B);   // 128 x 8 = 1024 blocks
    cd_pair_kernel<<<grid, CD_TPB>>>(p1, p2);
    cd_sum_kernel<<<1, CD_STPB>>>(out);
}